// round 2
// baseline (speedup 1.0000x reference)
#include <cuda_runtime.h>
#include <math.h>

#define NROWS 4096
#define DIM   1024
#define EPS   1e-8f

// Scratch for row norms (no device allocation allowed -> __device__ globals)
__device__ float g_tn[NROWS];
__device__ float g_sn[NROWS];

// ---------------------------------------------------------------------------
// Row L2 norms for both matrices. blockIdx.x in [0, 8192): first 4096 rows of
// target, next 4096 rows of ss. 128 threads/block, float4 loads.
// ---------------------------------------------------------------------------
__global__ __launch_bounds__(128) void row_norms_kernel(
    const float* __restrict__ target, const float* __restrict__ ss)
{
    int row = blockIdx.x;
    bool is_t = row < NROWS;
    int r = is_t ? row : row - NROWS;
    const float4* p = (const float4*)((is_t ? target : ss) + (size_t)r * DIM);

    float s = 0.f;
    #pragma unroll
    for (int i = threadIdx.x; i < DIM / 4; i += 128) {
        float4 v = p[i];
        s += v.x * v.x + v.y * v.y + v.z * v.z + v.w * v.w;
    }

    // warp reduce
    #pragma unroll
    for (int off = 16; off > 0; off >>= 1)
        s += __shfl_down_sync(0xFFFFFFFFu, s, off);

    __shared__ float warp_sums[4];
    int lane = threadIdx.x & 31;
    int wid  = threadIdx.x >> 5;
    if (lane == 0) warp_sums[wid] = s;
    __syncthreads();

    if (threadIdx.x == 0) {
        float tot = warp_sums[0] + warp_sums[1] + warp_sums[2] + warp_sums[3];
        float n = sqrtf(tot);
        if (is_t) g_tn[r] = n; else g_sn[r] = n;
    }
}

// ---------------------------------------------------------------------------
// Fused NT-GEMM + cosine epilogue, double-buffered smem.
// C[i,j] = dot(A[i,:], B[j,:]) / max(tn[i]*sn[j], eps)
// Tiles: 128x128 output per block, BK=16, 256 threads, 8x8 per-thread.
// ---------------------------------------------------------------------------
#define BM 128
#define BN 128
#define BK 16
#define TM 8
#define TN 8

__global__ __launch_bounds__(256) void cosine_gemm_kernel(
    const float* __restrict__ A,   // target [4096,1024] row-major
    const float* __restrict__ B,   // ss     [4096,1024] row-major
    float* __restrict__ C)         // out    [4096,4096]
{
    __shared__ float As[2][BK][BM];   // transposed: As[buf][k][i]
    __shared__ float Bs[2][BK][BN];

    const int tid = threadIdx.x;
    const int bm  = blockIdx.y * BM;
    const int bn  = blockIdx.x * BN;

    // Loader mapping: tid -> (row 0..63, k-quad 0..3); two passes cover 128 rows.
    const int lr = tid >> 2;          // 0..63
    const int lk = (tid & 3) * 4;     // 0,4,8,12

    // Compute mapping: 16x16 threads, each owns an 8x8 micro-tile.
    const int tr = (tid >> 4) * TM;   // 0..120
    const int tc = (tid & 15) * TN;   // 0..120

    const float* Ab = A + (size_t)bm * DIM;
    const float* Bb = B + (size_t)bn * DIM;

    float acc[TM][TN];
    #pragma unroll
    for (int i = 0; i < TM; i++)
        #pragma unroll
        for (int j = 0; j < TN; j++) acc[i][j] = 0.f;

    // ---- prologue: load tile 0 into buffer 0 ----
    #pragma unroll
    for (int h = 0; h < 2; h++) {
        int row = lr + h * 64;
        float4 va = *(const float4*)(Ab + (size_t)row * DIM + lk);
        As[0][lk + 0][row] = va.x;
        As[0][lk + 1][row] = va.y;
        As[0][lk + 2][row] = va.z;
        As[0][lk + 3][row] = va.w;
        float4 vb = *(const float4*)(Bb + (size_t)row * DIM + lk);
        Bs[0][lk + 0][row] = vb.x;
        Bs[0][lk + 1][row] = vb.y;
        Bs[0][lk + 2][row] = vb.z;
        Bs[0][lk + 3][row] = vb.w;
    }
    __syncthreads();

    int buf = 0;
    for (int k0 = 0; k0 < DIM; k0 += BK) {
        const int nxt = buf ^ 1;
        const bool have_next = (k0 + BK) < DIM;

        // ---- issue global loads for next tile (registers) ----
        float4 va0, vb0, va1, vb1;
        if (have_next) {
            int knext = k0 + BK;
            va0 = *(const float4*)(Ab + (size_t)(lr     ) * DIM + knext + lk);
            vb0 = *(const float4*)(Bb + (size_t)(lr     ) * DIM + knext + lk);
            va1 = *(const float4*)(Ab + (size_t)(lr + 64) * DIM + knext + lk);
            vb1 = *(const float4*)(Bb + (size_t)(lr + 64) * DIM + knext + lk);
        }

        // ---- 16 outer-product steps on current buffer ----
        #pragma unroll
        for (int k = 0; k < BK; k++) {
            float a[TM], b[TN];
            *(float4*)&a[0] = *(const float4*)&As[buf][k][tr];
            *(float4*)&a[4] = *(const float4*)&As[buf][k][tr + 4];
            *(float4*)&b[0] = *(const float4*)&Bs[buf][k][tc];
            *(float4*)&b[4] = *(const float4*)&Bs[buf][k][tc + 4];
            #pragma unroll
            for (int i = 0; i < TM; i++)
                #pragma unroll
                for (int j = 0; j < TN; j++)
                    acc[i][j] = fmaf(a[i], b[j], acc[i][j]);
        }

        // ---- write next tile into other buffer ----
        if (have_next) {
            As[nxt][lk + 0][lr] = va0.x;
            As[nxt][lk + 1][lr] = va0.y;
            As[nxt][lk + 2][lr] = va0.z;
            As[nxt][lk + 3][lr] = va0.w;
            Bs[nxt][lk + 0][lr] = vb0.x;
            Bs[nxt][lk + 1][lr] = vb0.y;
            Bs[nxt][lk + 2][lr] = vb0.z;
            Bs[nxt][lk + 3][lr] = vb0.w;
            As[nxt][lk + 0][lr + 64] = va1.x;
            As[nxt][lk + 1][lr + 64] = va1.y;
            As[nxt][lk + 2][lr + 64] = va1.z;
            As[nxt][lk + 3][lr + 64] = va1.w;
            Bs[nxt][lk + 0][lr + 64] = vb1.x;
            Bs[nxt][lk + 1][lr + 64] = vb1.y;
            Bs[nxt][lk + 2][lr + 64] = vb1.z;
            Bs[nxt][lk + 3][lr + 64] = vb1.w;
            __syncthreads();
        }
        buf = nxt;
    }

    // ---- epilogue: divide by max(tn*sn, eps), vectorized stores ----
    float tn[TM], sn[TN];
    #pragma unroll
    for (int i = 0; i < TM; i++) tn[i] = g_tn[bm + tr + i];
    #pragma unroll
    for (int j = 0; j < TN; j++) sn[j] = g_sn[bn + tc + j];

    #pragma unroll
    for (int i = 0; i < TM; i++) {
        float* Crow = C + (size_t)(bm + tr + i) * NROWS + bn + tc;
        #pragma unroll
        for (int j4 = 0; j4 < TN; j4 += 4) {
            float4 v;
            v.x = acc[i][j4 + 0] / fmaxf(tn[i] * sn[j4 + 0], EPS);
            v.y = acc[i][j4 + 1] / fmaxf(tn[i] * sn[j4 + 1], EPS);
            v.z = acc[i][j4 + 2] / fmaxf(tn[i] * sn[j4 + 2], EPS);
            v.w = acc[i][j4 + 3] / fmaxf(tn[i] * sn[j4 + 3], EPS);
            *(float4*)(Crow + j4) = v;
        }
    }
}

// ---------------------------------------------------------------------------
extern "C" void kernel_launch(void* const* d_in, const int* in_sizes, int n_in,
                              void* d_out, int out_size)
{
    const float* target = (const float*)d_in[0];
    const float* ss     = (const float*)d_in[1];
    float* out          = (float*)d_out;

    row_norms_kernel<<<2 * NROWS, 128>>>(target, ss);

    dim3 grid(NROWS / BN, NROWS / BM);   // 32 x 32
    cosine_gemm_kernel<<<grid, 256>>>(target, ss, out);
}

// round 4
// speedup vs baseline: 3.0278x; 3.0278x over previous
#include <cuda_runtime.h>
#include <cuda_bf16.h>
#include <math.h>
#include <stdint.h>

#define NROWS 4096
#define DIM   1024
#define EPS   1e-8f

// GEMM tiling
#define BM 128
#define BN 128
#define BK 64                      // bf16 K per smem tile (128 B rows -> SW128 swizzle)
#define NTILES_K (DIM / BK)        // 16
#define NPARTS 3                   // hi*hi, hi*lo, lo*hi
#define NTILES (NPARTS * NTILES_K) // 48

// dynamic smem layout: double-buffered A/B tiles, 16 KB each
#define SMEM_A0 0
#define SMEM_A1 16384
#define SMEM_B0 32768
#define SMEM_B1 49152
#define SMEM_TOTAL 65536

// Scratch (no device allocation allowed -> __device__ globals)
__device__ __nv_bfloat16 g_Ahi[NROWS * DIM];
__device__ __nv_bfloat16 g_Alo[NROWS * DIM];
__device__ __nv_bfloat16 g_Bhi[NROWS * DIM];
__device__ __nv_bfloat16 g_Blo[NROWS * DIM];
__device__ float g_tn[NROWS];
__device__ float g_sn[NROWS];

// ---------------------------------------------------------------------------
// helpers
// ---------------------------------------------------------------------------
__device__ __forceinline__ uint32_t smem_u32(const void* p) {
    uint32_t a;
    asm("{ .reg .u64 t; cvta.to.shared.u64 t, %1; cvt.u32.u64 %0, t; }"
        : "=r"(a) : "l"(p));
    return a;
}
__device__ __forceinline__ void cp16(uint32_t dst, const void* src) {
    asm volatile("cp.async.cg.shared.global [%0], [%1], 16;"
                 :: "r"(dst), "l"(src));
}
#define CP_COMMIT() asm volatile("cp.async.commit_group;" ::: "memory")
#define CP_WAIT(n)  asm volatile("cp.async.wait_group %0;" :: "n"(n) : "memory")

__device__ __forceinline__ uint32_t swz(uint32_t o) {   // SW128: xor bits[6:4] ^= bits[9:7]
    return o ^ ((o >> 3) & 0x70);
}
__device__ __forceinline__ void ldsm4(uint32_t& r0, uint32_t& r1,
                                      uint32_t& r2, uint32_t& r3, uint32_t a) {
    asm volatile("ldmatrix.sync.aligned.m8n8.x4.shared.b16 {%0,%1,%2,%3}, [%4];"
                 : "=r"(r0), "=r"(r1), "=r"(r2), "=r"(r3) : "r"(a));
}
__device__ __forceinline__ void mma16816(float* d, const uint32_t* a,
                                         uint32_t b0, uint32_t b1) {
    asm volatile(
        "mma.sync.aligned.m16n8k16.row.col.f32.bf16.bf16.f32 "
        "{%0,%1,%2,%3}, {%4,%5,%6,%7}, {%8,%9}, {%0,%1,%2,%3};"
        : "+f"(d[0]), "+f"(d[1]), "+f"(d[2]), "+f"(d[3])
        : "r"(a[0]), "r"(a[1]), "r"(a[2]), "r"(a[3]), "r"(b0), "r"(b1));
}

// ---------------------------------------------------------------------------
// Preprocess: per-row norm + bf16 hi/lo split for both matrices.
// blockIdx.x in [0, 8192): first 4096 = target, next 4096 = ss.
// ---------------------------------------------------------------------------
__global__ __launch_bounds__(128) void prep_kernel(
    const float* __restrict__ target, const float* __restrict__ ss)
{
    int row = blockIdx.x;
    bool is_t = row < NROWS;
    int r = is_t ? row : row - NROWS;
    const float* src = (is_t ? target : ss) + (size_t)r * DIM;
    __nv_bfloat16* hi = (is_t ? g_Ahi : g_Bhi) + (size_t)r * DIM;
    __nv_bfloat16* lo = (is_t ? g_Alo : g_Blo) + (size_t)r * DIM;

    float s = 0.f;
    #pragma unroll
    for (int j = 0; j < DIM / 128; j++) {
        int i = threadIdx.x + j * 128;
        float x = src[i];
        s += x * x;
        __nv_bfloat16 h = __float2bfloat16(x);
        __nv_bfloat16 l = __float2bfloat16(x - __bfloat162float(h));
        hi[i] = h;
        lo[i] = l;
    }
    #pragma unroll
    for (int off = 16; off > 0; off >>= 1)
        s += __shfl_down_sync(0xFFFFFFFFu, s, off);
    __shared__ float ws[4];
    if ((threadIdx.x & 31) == 0) ws[threadIdx.x >> 5] = s;
    __syncthreads();
    if (threadIdx.x == 0) {
        float n = sqrtf(ws[0] + ws[1] + ws[2] + ws[3]);
        if (is_t) g_tn[r] = n; else g_sn[r] = n;
    }
}

// ---------------------------------------------------------------------------
// Load one (A 128x64, B 128x64) bf16 tile into smem buffer via cp.async.
// tile: 0..47 -> part = tile/16 (0: hi*hi, 1: hi*lo, 2: lo*hi), k0 = (tile%16)*64
// ---------------------------------------------------------------------------
__device__ __forceinline__ void load_tile(uint32_t smem_base, int tile, int buf,
                                          int bm, int bn, int tid)
{
    int part = tile >> 4;
    int kk = (tile & 15) * BK;
    const __nv_bfloat16* Asrc = (part == 2) ? g_Alo : g_Ahi;
    const __nv_bfloat16* Bsrc = (part == 1) ? g_Blo : g_Bhi;
    uint32_t abase = smem_base + (buf ? SMEM_A1 : SMEM_A0);
    uint32_t bbase = smem_base + (buf ? SMEM_B1 : SMEM_B0);

    #pragma unroll
    for (int i = 0; i < 4; i++) {       // 1024 chunks = 128 rows x 8 x 16B
        int ch = tid + i * 256;
        int r = ch >> 3, c = ch & 7;
        cp16(abase + swz((uint32_t)(r * 128 + c * 16)),
             Asrc + (size_t)(bm + r) * DIM + kk + c * 8);
        cp16(bbase + swz((uint32_t)(r * 128 + c * 16)),
             Bsrc + (size_t)(bn + r) * DIM + kk + c * 8);
    }
}

// ---------------------------------------------------------------------------
// bf16-split mma.sync GEMM + cosine epilogue.
// 128x128 CTA tile, 8 warps (2 M x 4 N), warp tile 64x32, m16n8k16 frags.
// ---------------------------------------------------------------------------
__global__ __launch_bounds__(256) void cosine_mma_kernel(float* __restrict__ C)
{
    extern __shared__ char smem[];
    const uint32_t smem_base = smem_u32(smem);
    const int tid  = threadIdx.x;
    const int wid  = tid >> 5;
    const int lane = tid & 31;
    const int bm = blockIdx.y * BM;
    const int bn = blockIdx.x * BN;

    const int warp_m = (wid >> 2) * 64;  // 0 or 64
    const int warp_n = (wid & 3) * 32;   // 0,32,64,96

    // ldmatrix per-lane addressing: matrix = lane>>3, row-in-matrix = lane&7
    const int lrow = ((lane >> 3) & 1) * 8 + (lane & 7);  // row within 16-row frag
    const int lcolhalf = (lane >> 4);                     // 0: k0-7, 1: k8-15

    float acc[4][4][4];
    #pragma unroll
    for (int i = 0; i < 4; i++)
        #pragma unroll
        for (int j = 0; j < 4; j++)
            #pragma unroll
            for (int v = 0; v < 4; v++) acc[i][j][v] = 0.f;

    // prologue
    load_tile(smem_base, 0, 0, bm, bn, tid);
    CP_COMMIT();

    for (int t = 0; t < NTILES; t++) {
        const int buf = t & 1;
        if (t + 1 < NTILES) {
            load_tile(smem_base, t + 1, buf ^ 1, bm, bn, tid);
            CP_COMMIT();
            CP_WAIT(1);
        } else {
            CP_WAIT(0);
        }
        __syncthreads();

        const uint32_t abase = smem_base + (buf ? SMEM_A1 : SMEM_A0);
        const uint32_t bbase = smem_base + (buf ? SMEM_B1 : SMEM_B0);

        #pragma unroll
        for (int ks = 0; ks < 4; ks++) {       // 4 x k16 per tile
            const int col16 = ks * 2 + lcolhalf;

            uint32_t a[4][4];
            #pragma unroll
            for (int mf = 0; mf < 4; mf++) {
                uint32_t addr = abase +
                    swz((uint32_t)((warp_m + mf * 16 + lrow) * 128 + col16 * 16));
                ldsm4(a[mf][0], a[mf][1], a[mf][2], a[mf][3], addr);
            }
            uint32_t b[4][4];                  // b[pair][4]: m0=(n0-7,kLo) m1=(n8-15,kLo) m2=(n0-7,kHi) m3=(n8-15,kHi)
            #pragma unroll
            for (int np = 0; np < 2; np++) {
                uint32_t addr = bbase +
                    swz((uint32_t)((warp_n + np * 16 + lrow) * 128 + col16 * 16));
                ldsm4(b[np][0], b[np][1], b[np][2], b[np][3], addr);
            }

            #pragma unroll
            for (int mf = 0; mf < 4; mf++) {
                #pragma unroll
                for (int nf = 0; nf < 4; nf++) {
                    const int np = nf >> 1, hi = nf & 1;
                    mma16816(acc[mf][nf], a[mf], b[np][hi], b[np][2 + hi]);
                }
            }
        }
        __syncthreads();
    }

    // ---- epilogue: cosine normalize + store ----
    #pragma unroll
    for (int mf = 0; mf < 4; mf++) {
        const int row0 = bm + warp_m + mf * 16 + (lane >> 2);
        const int row1 = row0 + 8;
        const float tn0 = g_tn[row0];
        const float tn1 = g_tn[row1];
        float* Cr0 = C + (size_t)row0 * NROWS;
        float* Cr1 = C + (size_t)row1 * NROWS;
        #pragma unroll
        for (int nf = 0; nf < 4; nf++) {
            const int col = bn + warp_n + nf * 8 + (lane & 3) * 2;
            const float sn0 = g_sn[col];
            const float sn1 = g_sn[col + 1];
            float2 v0, v1;
            v0.x = acc[mf][nf][0] / fmaxf(tn0 * sn0, EPS);
            v0.y = acc[mf][nf][1] / fmaxf(tn0 * sn1, EPS);
            v1.x = acc[mf][nf][2] / fmaxf(tn1 * sn0, EPS);
            v1.y = acc[mf][nf][3] / fmaxf(tn1 * sn1, EPS);
            *(float2*)(Cr0 + col) = v0;
            *(float2*)(Cr1 + col) = v1;
        }
    }
}

// ---------------------------------------------------------------------------
extern "C" void kernel_launch(void* const* d_in, const int* in_sizes, int n_in,
                              void* d_out, int out_size)
{
    const float* target = (const float*)d_in[0];
    const float* ss     = (const float*)d_in[1];
    float* out          = (float*)d_out;

    cudaFuncSetAttribute(cosine_mma_kernel,
                         cudaFuncAttributeMaxDynamicSharedMemorySize, SMEM_TOTAL);

    prep_kernel<<<2 * NROWS, 128>>>(target, ss);

    dim3 grid(NROWS / BN, NROWS / BM);   // 32 x 32
    cosine_mma_kernel<<<grid, 256, SMEM_TOTAL>>>(out);
}

// round 5
// speedup vs baseline: 3.1501x; 1.0404x over previous
#include <cuda_runtime.h>
#include <cuda_bf16.h>
#include <math.h>
#include <stdint.h>

#define NROWS 4096
#define DIM   1024
#define EPS   1e-8f

// GEMM tiling
#define BM 128
#define BN 128
#define BK 64                      // bf16 K per smem tile (128 B rows -> SW128 swizzle)
#define NTILES_K (DIM / BK)        // 16
#define NPARTS 3                   // hi*hi, hi*lo, lo*hi
#define NTILES (NPARTS * NTILES_K) // 48

// dynamic smem layout: double-buffered A/B tiles, 16 KB each
#define SMEM_A0 0
#define SMEM_A1 16384
#define SMEM_B0 32768
#define SMEM_B1 49152
#define SMEM_TOTAL 65536

// Scratch (no device allocation allowed -> __device__ globals)
__device__ __nv_bfloat16 g_Ahi[NROWS * DIM];
__device__ __nv_bfloat16 g_Alo[NROWS * DIM];
__device__ __nv_bfloat16 g_Bhi[NROWS * DIM];
__device__ __nv_bfloat16 g_Blo[NROWS * DIM];
__device__ float g_tn[NROWS];
__device__ float g_sn[NROWS];

// ---------------------------------------------------------------------------
// helpers
// ---------------------------------------------------------------------------
__device__ __forceinline__ uint32_t smem_u32(const void* p) {
    uint32_t a;
    asm("{ .reg .u64 t; cvta.to.shared.u64 t, %1; cvt.u32.u64 %0, t; }"
        : "=r"(a) : "l"(p));
    return a;
}
__device__ __forceinline__ void cp16(uint32_t dst, const void* src) {
    asm volatile("cp.async.cg.shared.global [%0], [%1], 16;"
                 :: "r"(dst), "l"(src));
}
#define CP_COMMIT() asm volatile("cp.async.commit_group;" ::: "memory")
#define CP_WAIT(n)  asm volatile("cp.async.wait_group %0;" :: "n"(n) : "memory")

__device__ __forceinline__ uint32_t swz(uint32_t o) {   // SW128: bits[6:4] ^= bits[9:7]
    return o ^ ((o >> 3) & 0x70);
}
__device__ __forceinline__ void ldsm4(uint32_t* r, uint32_t a) {
    asm volatile("ldmatrix.sync.aligned.m8n8.x4.shared.b16 {%0,%1,%2,%3}, [%4];"
                 : "=r"(r[0]), "=r"(r[1]), "=r"(r[2]), "=r"(r[3]) : "r"(a));
}
__device__ __forceinline__ void mma16816(float* d, const uint32_t* a,
                                         uint32_t b0, uint32_t b1) {
    asm volatile(
        "mma.sync.aligned.m16n8k16.row.col.f32.bf16.bf16.f32 "
        "{%0,%1,%2,%3}, {%4,%5,%6,%7}, {%8,%9}, {%0,%1,%2,%3};"
        : "+f"(d[0]), "+f"(d[1]), "+f"(d[2]), "+f"(d[3])
        : "r"(a[0]), "r"(a[1]), "r"(a[2]), "r"(a[3]), "r"(b0), "r"(b1));
}

// ---------------------------------------------------------------------------
// Preprocess: per-row norm + bf16 hi/lo split for both matrices.
// ---------------------------------------------------------------------------
__global__ __launch_bounds__(128) void prep_kernel(
    const float* __restrict__ target, const float* __restrict__ ss)
{
    int row = blockIdx.x;
    bool is_t = row < NROWS;
    int r = is_t ? row : row - NROWS;
    const float* src = (is_t ? target : ss) + (size_t)r * DIM;
    __nv_bfloat16* hi = (is_t ? g_Ahi : g_Bhi) + (size_t)r * DIM;
    __nv_bfloat16* lo = (is_t ? g_Alo : g_Blo) + (size_t)r * DIM;

    float s = 0.f;
    #pragma unroll
    for (int j = 0; j < DIM / 128; j++) {
        int i = threadIdx.x + j * 128;
        float x = src[i];
        s += x * x;
        __nv_bfloat16 h = __float2bfloat16(x);
        __nv_bfloat16 l = __float2bfloat16(x - __bfloat162float(h));
        hi[i] = h;
        lo[i] = l;
    }
    #pragma unroll
    for (int off = 16; off > 0; off >>= 1)
        s += __shfl_down_sync(0xFFFFFFFFu, s, off);
    __shared__ float ws[4];
    if ((threadIdx.x & 31) == 0) ws[threadIdx.x >> 5] = s;
    __syncthreads();
    if (threadIdx.x == 0) {
        float n = sqrtf(ws[0] + ws[1] + ws[2] + ws[3]);
        if (is_t) g_tn[r] = n; else g_sn[r] = n;
    }
}

// ---------------------------------------------------------------------------
// bf16-split mma.sync GEMM + cosine epilogue.
// 128x128 CTA tile, 8 warps (2 M x 4 N), warp tile 64x32, m16n8k16 frags.
// All swizzle math hoisted; fragment double-buffer across k-steps.
// ---------------------------------------------------------------------------
__global__ __launch_bounds__(256, 2) void cosine_mma_kernel(float* __restrict__ C)
{
    extern __shared__ char smem[];
    const uint32_t smem_base = smem_u32(smem);
    const int tid  = threadIdx.x;
    const int wid  = tid >> 5;
    const int lane = tid & 31;
    const int bm = blockIdx.y * BM;
    const int bn = blockIdx.x * BN;

    const int warp_m = (wid >> 2) * 64;  // 0 or 64
    const int warp_n = (wid & 3) * 32;   // 0,32,64,96

    // ---- loader address precompute (identical mapping to R4) ----
    // pass i covers rows (tid>>3)+i*32, col chunk (tid&7)*16 bytes.
    const int ldr = tid >> 3;            // 0..31
    const int ldc = tid & 7;             // 0..7
    const uint32_t dst0 = swz((uint32_t)(ldr * 128 + ldc * 16));  // +i*4096 per pass
    const size_t srcA_off = (size_t)(bm + ldr) * DIM + ldc * 8;
    const size_t srcB_off = (size_t)(bn + ldr) * DIM + ldc * 8;

    // ---- ldmatrix address precompute ----
    // swz(row*128 + c) = row*128 + (c ^ ((row&7)<<4)) for c in [0,128)
    const int lrow = ((lane >> 3) & 1) * 8 + (lane & 7);
    const int cx   = (lane >> 4) * 16;          // k-half select
    const uint32_t xorv = (uint32_t)((lrow & 7) * 16);
    uint32_t aoff[4], boff[2], colx[4];
    #pragma unroll
    for (int mf = 0; mf < 4; mf++)
        aoff[mf] = (uint32_t)((warp_m + mf * 16 + lrow) * 128);
    #pragma unroll
    for (int np = 0; np < 2; np++)
        boff[np] = (uint32_t)((warp_n + np * 16 + lrow) * 128);
    #pragma unroll
    for (int ks = 0; ks < 4; ks++)
        colx[ks] = (uint32_t)(ks * 32 + cx) ^ xorv;

    float acc[4][4][4];
    #pragma unroll
    for (int i = 0; i < 4; i++)
        #pragma unroll
        for (int j = 0; j < 4; j++)
            #pragma unroll
            for (int v = 0; v < 4; v++) acc[i][j][v] = 0.f;

    // ---- prologue: tile 0 ----
    {
        const __nv_bfloat16* pA = g_Ahi + srcA_off;
        const __nv_bfloat16* pB = g_Bhi + srcB_off;
        #pragma unroll
        for (int i = 0; i < 4; i++) {
            cp16(smem_base + SMEM_A0 + dst0 + i * 4096, pA + (size_t)i * 32 * DIM);
            cp16(smem_base + SMEM_B0 + dst0 + i * 4096, pB + (size_t)i * 32 * DIM);
        }
        CP_COMMIT();
    }

    for (int t = 0; t < NTILES; t++) {
        const int buf = t & 1;
        if (t + 1 < NTILES) {
            const int tn1 = t + 1;
            const int part = tn1 >> 4;
            const int kk = (tn1 & 15) * BK;
            const __nv_bfloat16* pA = ((part == 2) ? g_Alo : g_Ahi) + srcA_off + kk;
            const __nv_bfloat16* pB = ((part == 1) ? g_Blo : g_Bhi) + srcB_off + kk;
            const uint32_t da = smem_base + (buf ? SMEM_A0 : SMEM_A1) + dst0;
            const uint32_t db = smem_base + (buf ? SMEM_B0 : SMEM_B1) + dst0;
            #pragma unroll
            for (int i = 0; i < 4; i++) {
                cp16(da + i * 4096, pA + (size_t)i * 32 * DIM);
                cp16(db + i * 4096, pB + (size_t)i * 32 * DIM);
            }
            CP_COMMIT();
            CP_WAIT(1);
        } else {
            CP_WAIT(0);
        }
        __syncthreads();

        const uint32_t ab = smem_base + (buf ? SMEM_A1 : SMEM_A0);
        const uint32_t bb = smem_base + (buf ? SMEM_B1 : SMEM_B0);

        uint32_t afr[2][4][4], bfr[2][2][4];
        // preload ks=0 fragments
        #pragma unroll
        for (int mf = 0; mf < 4; mf++) ldsm4(afr[0][mf], ab + aoff[mf] + colx[0]);
        #pragma unroll
        for (int np = 0; np < 2; np++) ldsm4(bfr[0][np], bb + boff[np] + colx[0]);

        #pragma unroll
        for (int ks = 0; ks < 4; ks++) {
            const int cur = ks & 1;
            if (ks < 3) {
                const int nxt = cur ^ 1;
                #pragma unroll
                for (int mf = 0; mf < 4; mf++)
                    ldsm4(afr[nxt][mf], ab + aoff[mf] + colx[ks + 1]);
                #pragma unroll
                for (int np = 0; np < 2; np++)
                    ldsm4(bfr[nxt][np], bb + boff[np] + colx[ks + 1]);
            }
            #pragma unroll
            for (int mf = 0; mf < 4; mf++) {
                #pragma unroll
                for (int nf = 0; nf < 4; nf++) {
                    const int np = nf >> 1, hi = nf & 1;
                    mma16816(acc[mf][nf], afr[cur][mf],
                             bfr[cur][np][hi], bfr[cur][np][2 + hi]);
                }
            }
        }
        __syncthreads();
    }

    // ---- epilogue: cosine normalize + store ----
    #pragma unroll
    for (int mf = 0; mf < 4; mf++) {
        const int row0 = bm + warp_m + mf * 16 + (lane >> 2);
        const int row1 = row0 + 8;
        const float tn0 = g_tn[row0];
        const float tn1 = g_tn[row1];
        float* Cr0 = C + (size_t)row0 * NROWS;
        float* Cr1 = C + (size_t)row1 * NROWS;
        #pragma unroll
        for (int nf = 0; nf < 4; nf++) {
            const int col = bn + warp_n + nf * 8 + (lane & 3) * 2;
            const float sn0 = g_sn[col];
            const float sn1 = g_sn[col + 1];
            float2 v0, v1;
            v0.x = acc[mf][nf][0] / fmaxf(tn0 * sn0, EPS);
            v0.y = acc[mf][nf][1] / fmaxf(tn0 * sn1, EPS);
            v1.x = acc[mf][nf][2] / fmaxf(tn1 * sn0, EPS);
            v1.y = acc[mf][nf][3] / fmaxf(tn1 * sn1, EPS);
            *(float2*)(Cr0 + col) = v0;
            *(float2*)(Cr1 + col) = v1;
        }
    }
}

// ---------------------------------------------------------------------------
extern "C" void kernel_launch(void* const* d_in, const int* in_sizes, int n_in,
                              void* d_out, int out_size)
{
    const float* target = (const float*)d_in[0];
    const float* ss     = (const float*)d_in[1];
    float* out          = (float*)d_out;

    cudaFuncSetAttribute(cosine_mma_kernel,
                         cudaFuncAttributeMaxDynamicSharedMemorySize, SMEM_TOTAL);

    prep_kernel<<<2 * NROWS, 128>>>(target, ss);

    dim3 grid(NROWS / BN, NROWS / BM);   // 32 x 32
    cosine_mma_kernel<<<grid, 256, SMEM_TOTAL>>>(out);
}